// round 13
// baseline (speedup 1.0000x reference)
#include <cuda_runtime.h>

// Morphological opening (erosion -> dilation), 3x3 CROSS SE, kornia border
// semantics. Register rolling-row pipeline, zero SMEM, ONE launch.
// 8 columns per lane (2x float4); warp covers 256 cols, 4 warps = full row.

#define W 1024
#define H 1024
#define STRIP_H 16
#define BIGV 1e4f
#define FULL 0xffffffffu

struct F8 { float4 a, b; };

__device__ __forceinline__ float fmin3(float x, float y, float z) { return fminf(fminf(x, y), z); }
__device__ __forceinline__ float fmax3(float x, float y, float z) { return fmaxf(fmaxf(x, y), z); }

// Erosion of the middle row rb (ra above, rc below). s1b = input at (row of rb, c1).
__device__ __forceinline__ F8 ero8(const F8& ra, const F8& rb, const F8& rc,
                                   float s1b, bool isL, bool isR)
{
    float lw = __shfl_up_sync(FULL, rb.b.w, 1);   if (isL) lw = s1b;
    float rw = __shfl_down_sync(FULL, rb.a.x, 1); if (isR) rw = s1b;
    F8 e;
    e.a.x = fminf(fmin3(ra.a.x, rb.a.x, rc.a.x), fminf(lw,     rb.a.y));
    e.a.y = fminf(fmin3(ra.a.y, rb.a.y, rc.a.y), fminf(rb.a.x, rb.a.z));
    e.a.z = fminf(fmin3(ra.a.z, rb.a.z, rc.a.z), fminf(rb.a.y, rb.a.w));
    e.a.w = fminf(fmin3(ra.a.w, rb.a.w, rc.a.w), fminf(rb.a.z, rb.b.x));
    e.b.x = fminf(fmin3(ra.b.x, rb.b.x, rc.b.x), fminf(rb.a.w, rb.b.y));
    e.b.y = fminf(fmin3(ra.b.y, rb.b.y, rc.b.y), fminf(rb.b.x, rb.b.z));
    e.b.z = fminf(fmin3(ra.b.z, rb.b.z, rc.b.z), fminf(rb.b.y, rb.b.w));
    e.b.w = fminf(fmin3(ra.b.w, rb.b.w, rc.b.w), fminf(rb.b.z, rw));
    return e;
}

// Dilation combining erosion rows ep (above), ec (center), en (below).
__device__ __forceinline__ F8 dil8(const F8& ep, const F8& ec, const F8& en,
                                   float eEdge, bool isL, bool isR)
{
    float lw = __shfl_up_sync(FULL, ec.b.w, 1);   if (isL) lw = eEdge;
    float rw = __shfl_down_sync(FULL, ec.a.x, 1); if (isR) rw = eEdge;
    F8 d;
    d.a.x = fmaxf(fmax3(ep.a.x, ec.a.x, en.a.x), fmaxf(lw,     ec.a.y));
    d.a.y = fmaxf(fmax3(ep.a.y, ec.a.y, en.a.y), fmaxf(ec.a.x, ec.a.z));
    d.a.z = fmaxf(fmax3(ep.a.z, ec.a.z, en.a.z), fmaxf(ec.a.y, ec.a.w));
    d.a.w = fmaxf(fmax3(ep.a.w, ec.a.w, en.a.w), fmaxf(ec.a.z, ec.b.x));
    d.b.x = fmaxf(fmax3(ep.b.x, ec.b.x, en.b.x), fmaxf(ec.a.w, ec.b.y));
    d.b.y = fmaxf(fmax3(ep.b.y, ec.b.y, en.b.y), fmaxf(ec.b.x, ec.b.z));
    d.b.z = fmaxf(fmax3(ep.b.z, ec.b.z, en.b.z), fmaxf(ec.b.y, ec.b.w));
    d.b.w = fmaxf(fmax3(ep.b.w, ec.b.w, en.b.w), fmaxf(ec.b.z, rw));
    return d;
}

__device__ __forceinline__ F8 ld8(const float* p)
{
    F8 r;
    r.a = *reinterpret_cast<const float4*>(p);
    r.b = *reinterpret_cast<const float4*>(p + 4);
    return r;
}
__device__ __forceinline__ void st8(float* p, const F8& v)
{
    *reinterpret_cast<float4*>(p) = v.a;
    *reinterpret_cast<float4*>(p + 4) = v.b;
}

__global__ __launch_bounds__(128, 8)
void opening_kernel(const float* __restrict__ img, float* __restrict__ out)
{
    const int lane = threadIdx.x & 31;
    const int warp = threadIdx.x >> 5;
    const int gx = warp * 256 + lane * 8;       // first of 8 owned columns
    const int ys = blockIdx.y * STRIP_H;
    const size_t plane = (size_t)blockIdx.z * (size_t)(W * H);
    const float* __restrict__ src = img + plane;
    float* __restrict__ dst = out + plane;

    const bool isL = (lane == 0);
    const bool isR = (lane == 31);
    const bool isEdge = isL | isR;
    const int c1 = isL ? gx - 1 : gx + 8;
    const int c2 = isL ? gx - 2 : gx + 9;
    const bool ok1 = isEdge && ((unsigned)c1 < (unsigned)W);
    const bool ok2 = isEdge && ((unsigned)c2 < (unsigned)W);

    if (ys > 0 && ys + STRIP_H < H) {
        // ================= FAST PATH: no row bounds checks =================
        const float* pv = src + (size_t)(ys - 2) * W + gx;
        const float* p1 = src + (size_t)(ys - 2) * W + (ok1 ? c1 : gx);
        const float* p2 = src + (size_t)(ys - 2) * W + (ok2 ? c2 : gx);
        float* pw = dst + (size_t)ys * W + gx;

        F8 A  = ld8(pv);  pv += W;
        F8 Bv = ld8(pv);  pv += W;
        F8 C  = ld8(pv);  pv += W;
        F8 D  = ld8(pv);  pv += W;
        float s1B = ok1 ? p1[W]   : BIGV;
        float s1C = ok1 ? p1[2*W] : BIGV;
        float s1D = ok1 ? p1[3*W] : BIGV;
        float s2C = ok2 ? p2[2*W] : BIGV;
        p1 += 3 * W;
        p2 += 2 * W;

        F8 e_prev = ero8(A, Bv, C, s1B, isL, isR);
        F8 e_cur  = ero8(Bv, C, D, s1C, isL, isR);
        float Xc = isL ? C.a.x : C.b.w;
        float eEdge_cur = ok1 ? fminf(fmin3(s1B, s1C, s1D), fminf(s2C, Xc)) : -BIGV;

        F8 in_a = C, in_b = D;
        float s1_a = s1C, s1_b = s1D;

        #pragma unroll 4
        for (int i = 0; i < STRIP_H; ++i) {
            F8 in_c = ld8(pv);  pv += W;
            float s1_c = ok1 ? p1[W] : BIGV;  p1 += W;
            float s2m  = ok2 ? p2[W] : BIGV;  p2 += W;

            F8 en = ero8(in_a, in_b, in_c, s1_b, isL, isR);
            float X = isL ? in_b.a.x : in_b.b.w;
            float eEdgeN = ok1 ? fminf(fmin3(s1_a, s1_b, s1_c), fminf(s2m, X)) : -BIGV;

            F8 d = dil8(e_prev, e_cur, en, eEdge_cur, isL, isR);
            st8(pw, d);  pw += W;

            e_prev = e_cur; e_cur = en; eEdge_cur = eEdgeN;
            in_a = in_b; in_b = in_c;
            s1_a = s1_b; s1_b = s1_c;
        }
    } else {
        // ================= CHECKED PATH: strips 0 and 63 ===================
        auto loadv = [&](int row) -> F8 {
            if ((unsigned)row < (unsigned)H)
                return ld8(src + (size_t)row * W + gx);
            F8 r; r.a = make_float4(BIGV, BIGV, BIGV, BIGV); r.b = r.a;
            return r;
        };
        auto loadsc = [&](int row, int col, bool ok) -> float {
            return (ok && (unsigned)row < (unsigned)H) ? __ldg(src + (size_t)row * W + col) : BIGV;
        };
        auto neg8 = []() -> F8 {
            F8 r; r.a = make_float4(-BIGV, -BIGV, -BIGV, -BIGV); r.b = r.a;
            return r;
        };

        F8 A  = loadv(ys - 2);
        F8 Bv = loadv(ys - 1);
        F8 C  = loadv(ys);
        F8 D  = loadv(ys + 1);
        float s1B = loadsc(ys - 1, c1, ok1);
        float s1C = loadsc(ys,     c1, ok1);
        float s1D = loadsc(ys + 1, c1, ok1);
        float s2C = loadsc(ys,     c2, ok2);

        F8 e_prev = ero8(A, Bv, C, s1B, isL, isR);
        if (ys - 1 < 0) e_prev = neg8();
        F8 e_cur = ero8(Bv, C, D, s1C, isL, isR);
        float Xc = isL ? C.a.x : C.b.w;
        float eEdge_cur = ok1 ? fminf(fmin3(s1B, s1C, s1D), fminf(s2C, Xc)) : -BIGV;

        F8 in_a = C, in_b = D;
        float s1_a = s1C, s1_b = s1D;

        #pragma unroll 2
        for (int y = ys; y < ys + STRIP_H; ++y) {
            const int rn = y + 2;
            F8 in_c = loadv(rn);
            float s1_c = loadsc(rn,    c1, ok1);
            float s2m  = loadsc(y + 1, c2, ok2);

            F8 en = ero8(in_a, in_b, in_c, s1_b, isL, isR);
            float X = isL ? in_b.a.x : in_b.b.w;
            float eEdgeN = ok1 ? fminf(fmin3(s1_a, s1_b, s1_c), fminf(s2m, X)) : -BIGV;
            if (y + 1 >= H) { en = neg8(); eEdgeN = -BIGV; }

            F8 d = dil8(e_prev, e_cur, en, eEdge_cur, isL, isR);
            st8(dst + (size_t)y * W + gx, d);

            e_prev = e_cur; e_cur = en; eEdge_cur = eEdgeN;
            in_a = in_b; in_b = in_c;
            s1_a = s1_b; s1_b = s1_c;
        }
    }
}

extern "C" void kernel_launch(void* const* d_in, const int* in_sizes, int n_in,
                              void* d_out, int out_size)
{
    const float* img = (const float*)d_in[0];
    float* out = (float*)d_out;
    const int planes = in_sizes[0] / (W * H);   // 24

    dim3 block(128, 1, 1);                      // 4 warps x 256 cols = full row
    dim3 grid(1, H / STRIP_H, planes);          // 64 x 24 = 1536 blocks
    opening_kernel<<<grid, block>>>(img, out);
}

// round 15
// speedup vs baseline: 1.0133x; 1.0133x over previous
#include <cuda_runtime.h>

// Morphological opening (erosion -> dilation), 3x3 CROSS SE, kornia border
// semantics. Register rolling-row pipeline, zero SMEM, ONE launch.
// 4 cols/lane (float4), 8 warps = full row, STRIP_H=32 -> 768 blocks =
// exactly one wave at occupancy 6 (148 SMs x 6 = 888 slots).

#define W 1024
#define H 1024
#define STRIP_H 32
#define BIGV 1e4f
#define FULL 0xffffffffu

__device__ __forceinline__ float fmin3(float a, float b, float c) { return fminf(fminf(a, b), c); }
__device__ __forceinline__ float fmax3(float a, float b, float c) { return fmaxf(fmaxf(a, b), c); }

__global__ __launch_bounds__(256, 6)
void opening_kernel(const float* __restrict__ img, float* __restrict__ out)
{
    const int lane = threadIdx.x & 31;
    const int warp = threadIdx.x >> 5;
    const int gx = warp * 128 + lane * 4;
    const int ys = blockIdx.y * STRIP_H;
    const size_t plane = (size_t)blockIdx.z * (size_t)(W * H);
    const float* __restrict__ src = img + plane;
    float* __restrict__ dst = out + plane;

    const bool isL = (lane == 0);
    const bool isR = (lane == 31);
    const bool isEdge = isL | isR;
    const int c1 = isL ? gx - 1 : gx + 4;
    const int c2 = isL ? gx - 2 : gx + 5;
    const bool ok1 = isEdge && ((unsigned)c1 < (unsigned)W);
    const bool ok2 = isEdge && ((unsigned)c2 < (unsigned)W);

    if (ys > 0 && ys + STRIP_H < H) {
        // ================= FAST PATH: no row bounds checks =================
        const float* pv = src + (size_t)(ys - 2) * W + gx;
        const float* p1 = src + (size_t)(ys - 2) * W + (ok1 ? c1 : gx);
        const float* p2 = src + (size_t)(ys - 2) * W + (ok2 ? c2 : gx);
        float* pw = dst + (size_t)ys * W + gx;

        float4 A  = *(const float4*)pv;               pv += W;
        float4 Bv = *(const float4*)pv;               pv += W;
        float4 C  = *(const float4*)pv;               pv += W;
        float4 D  = *(const float4*)pv;               pv += W;
        float s1B = ok1 ? p1[W]   : BIGV;
        float s1C = ok1 ? p1[2*W] : BIGV;
        float s1D = ok1 ? p1[3*W] : BIGV;
        float s2C = ok2 ? p2[2*W] : BIGV;
        p1 += 3 * W;
        p2 += 2 * W;

        float4 e_prev;
        {
            float lw = __shfl_up_sync(FULL, Bv.w, 1);   if (isL) lw = s1B;
            float rw = __shfl_down_sync(FULL, Bv.x, 1); if (isR) rw = s1B;
            e_prev.x = fminf(fmin3(A.x, Bv.x, C.x), fminf(lw,   Bv.y));
            e_prev.y = fminf(fmin3(A.y, Bv.y, C.y), fminf(Bv.x, Bv.z));
            e_prev.z = fminf(fmin3(A.z, Bv.z, C.z), fminf(Bv.y, Bv.w));
            e_prev.w = fminf(fmin3(A.w, Bv.w, C.w), fminf(Bv.z, rw));
        }
        float4 e_cur;
        float  eEdge_cur;
        {
            float lw = __shfl_up_sync(FULL, C.w, 1);   if (isL) lw = s1C;
            float rw = __shfl_down_sync(FULL, C.x, 1); if (isR) rw = s1C;
            e_cur.x = fminf(fmin3(Bv.x, C.x, D.x), fminf(lw,  C.y));
            e_cur.y = fminf(fmin3(Bv.y, C.y, D.y), fminf(C.x, C.z));
            e_cur.z = fminf(fmin3(Bv.z, C.z, D.z), fminf(C.y, C.w));
            e_cur.w = fminf(fmin3(Bv.w, C.w, D.w), fminf(C.z, rw));
            float X = isL ? C.x : C.w;
            eEdge_cur = ok1 ? fminf(fmin3(s1B, s1C, s1D), fminf(s2C, X)) : -BIGV;
        }

        float4 in_a = C, in_b = D;
        float  s1_a = s1C, s1_b = s1D;

        #pragma unroll 4
        for (int i = 0; i < STRIP_H; ++i) {
            float4 in_c = *(const float4*)pv;  pv += W;
            float  s1_c = ok1 ? p1[W] : BIGV;  p1 += W;
            float  s2m  = ok2 ? p2[W] : BIGV;  p2 += W;

            float4 en;
            float  eEdgeN;
            {
                float lw = __shfl_up_sync(FULL, in_b.w, 1);   if (isL) lw = s1_b;
                float rw = __shfl_down_sync(FULL, in_b.x, 1); if (isR) rw = s1_b;
                en.x = fminf(fmin3(in_a.x, in_b.x, in_c.x), fminf(lw,     in_b.y));
                en.y = fminf(fmin3(in_a.y, in_b.y, in_c.y), fminf(in_b.x, in_b.z));
                en.z = fminf(fmin3(in_a.z, in_b.z, in_c.z), fminf(in_b.y, in_b.w));
                en.w = fminf(fmin3(in_a.w, in_b.w, in_c.w), fminf(in_b.z, rw));
                float X = isL ? in_b.x : in_b.w;
                eEdgeN = ok1 ? fminf(fmin3(s1_a, s1_b, s1_c), fminf(s2m, X)) : -BIGV;
            }

            float lwE = __shfl_up_sync(FULL, e_cur.w, 1);   if (isL) lwE = eEdge_cur;
            float rwE = __shfl_down_sync(FULL, e_cur.x, 1); if (isR) rwE = eEdge_cur;

            float4 d;
            d.x = fmaxf(fmax3(e_prev.x, e_cur.x, en.x), fmaxf(lwE,     e_cur.y));
            d.y = fmaxf(fmax3(e_prev.y, e_cur.y, en.y), fmaxf(e_cur.x, e_cur.z));
            d.z = fmaxf(fmax3(e_prev.z, e_cur.z, en.z), fmaxf(e_cur.y, e_cur.w));
            d.w = fmaxf(fmax3(e_prev.w, e_cur.w, en.w), fmaxf(e_cur.z, rwE));

            *(float4*)pw = d;  pw += W;

            e_prev = e_cur; e_cur = en; eEdge_cur = eEdgeN;
            in_a = in_b; in_b = in_c;
            s1_a = s1_b; s1_b = s1_c;
        }
    } else {
        // ================= CHECKED PATH: strips 0 and 31 ===================
        auto loadv = [&](int row) -> float4 {
            if ((unsigned)row < (unsigned)H)
                return *reinterpret_cast<const float4*>(src + (size_t)row * W + gx);
            return make_float4(BIGV, BIGV, BIGV, BIGV);
        };
        auto loadsc = [&](int row, int col, bool ok) -> float {
            return (ok && (unsigned)row < (unsigned)H) ? __ldg(src + (size_t)row * W + col) : BIGV;
        };

        float4 A  = loadv(ys - 2);
        float4 Bv = loadv(ys - 1);
        float4 C  = loadv(ys);
        float4 D  = loadv(ys + 1);
        float s1B = loadsc(ys - 1, c1, ok1);
        float s1C = loadsc(ys,     c1, ok1);
        float s1D = loadsc(ys + 1, c1, ok1);
        float s2C = loadsc(ys,     c2, ok2);

        float4 e_prev;
        {
            float lw = __shfl_up_sync(FULL, Bv.w, 1);   if (isL) lw = s1B;
            float rw = __shfl_down_sync(FULL, Bv.x, 1); if (isR) rw = s1B;
            e_prev.x = fminf(fmin3(A.x, Bv.x, C.x), fminf(lw,   Bv.y));
            e_prev.y = fminf(fmin3(A.y, Bv.y, C.y), fminf(Bv.x, Bv.z));
            e_prev.z = fminf(fmin3(A.z, Bv.z, C.z), fminf(Bv.y, Bv.w));
            e_prev.w = fminf(fmin3(A.w, Bv.w, C.w), fminf(Bv.z, rw));
            if (ys - 1 < 0) e_prev = make_float4(-BIGV, -BIGV, -BIGV, -BIGV);
        }
        float4 e_cur;
        float  eEdge_cur;
        {
            float lw = __shfl_up_sync(FULL, C.w, 1);   if (isL) lw = s1C;
            float rw = __shfl_down_sync(FULL, C.x, 1); if (isR) rw = s1C;
            e_cur.x = fminf(fmin3(Bv.x, C.x, D.x), fminf(lw,  C.y));
            e_cur.y = fminf(fmin3(Bv.y, C.y, D.y), fminf(C.x, C.z));
            e_cur.z = fminf(fmin3(Bv.z, C.z, D.z), fminf(C.y, C.w));
            e_cur.w = fminf(fmin3(Bv.w, C.w, D.w), fminf(C.z, rw));
            float X = isL ? C.x : C.w;
            eEdge_cur = ok1 ? fminf(fmin3(s1B, s1C, s1D), fminf(s2C, X)) : -BIGV;
        }

        float4 in_a = C, in_b = D;
        float  s1_a = s1C, s1_b = s1D;

        #pragma unroll 4
        for (int y = ys; y < ys + STRIP_H; ++y) {
            const int rn = y + 2;
            float4 in_c = loadv(rn);
            float  s1_c = loadsc(rn,    c1, ok1);
            float  s2m  = loadsc(y + 1, c2, ok2);

            float4 en;
            float  eEdgeN;
            {
                float lw = __shfl_up_sync(FULL, in_b.w, 1);   if (isL) lw = s1_b;
                float rw = __shfl_down_sync(FULL, in_b.x, 1); if (isR) rw = s1_b;
                en.x = fminf(fmin3(in_a.x, in_b.x, in_c.x), fminf(lw,     in_b.y));
                en.y = fminf(fmin3(in_a.y, in_b.y, in_c.y), fminf(in_b.x, in_b.z));
                en.z = fminf(fmin3(in_a.z, in_b.z, in_c.z), fminf(in_b.y, in_b.w));
                en.w = fminf(fmin3(in_a.w, in_b.w, in_c.w), fminf(in_b.z, rw));
                float X = isL ? in_b.x : in_b.w;
                eEdgeN = ok1 ? fminf(fmin3(s1_a, s1_b, s1_c), fminf(s2m, X)) : -BIGV;
                if (y + 1 >= H) {
                    en = make_float4(-BIGV, -BIGV, -BIGV, -BIGV);
                    eEdgeN = -BIGV;
                }
            }

            float lwE = __shfl_up_sync(FULL, e_cur.w, 1);   if (isL) lwE = eEdge_cur;
            float rwE = __shfl_down_sync(FULL, e_cur.x, 1); if (isR) rwE = eEdge_cur;

            float4 d;
            d.x = fmaxf(fmax3(e_prev.x, e_cur.x, en.x), fmaxf(lwE,     e_cur.y));
            d.y = fmaxf(fmax3(e_prev.y, e_cur.y, en.y), fmaxf(e_cur.x, e_cur.z));
            d.z = fmaxf(fmax3(e_prev.z, e_cur.z, en.z), fmaxf(e_cur.y, e_cur.w));
            d.w = fmaxf(fmax3(e_prev.w, e_cur.w, en.w), fmaxf(e_cur.z, rwE));

            *reinterpret_cast<float4*>(dst + (size_t)y * W + gx) = d;

            e_prev = e_cur; e_cur = en; eEdge_cur = eEdgeN;
            in_a = in_b; in_b = in_c;
            s1_a = s1_b; s1_b = s1_c;
        }
    }
}

extern "C" void kernel_launch(void* const* d_in, const int* in_sizes, int n_in,
                              void* d_out, int out_size)
{
    const float* img = (const float*)d_in[0];
    float* out = (float*)d_out;
    const int planes = in_sizes[0] / (W * H);   // 24

    dim3 block(256, 1, 1);                      // 8 warps x 128 cols = full row
    dim3 grid(1, H / STRIP_H, planes);          // 32 x 24 = 768 blocks (one wave)
    opening_kernel<<<grid, block>>>(img, out);
}